// round 2
// baseline (speedup 1.0000x reference)
#include <cuda_runtime.h>
#include <cuda_bf16.h>

// Attention with causal+padding mask (faithful to the reference's
// "masked iff future+pad == 1" semantics), fp32 SIMT baseline.
//
// One CTA = one (b, h, 16-row q-tile). Score row-block [16][2048] kept in
// SMEM across QK^T -> softmax -> weights write -> P@V. Single write of the
// 1.07 GB attention_weights output; K/V streamed from L2.

#define BB 4
#define HH 16
#define SS_ 2048
#define DD 64
#define TQ 16
#define NTHREADS 256

// smem layout (floats): scores[TQ][S] | Q[TQ][D] | Vtile[128][D]
#define SMEM_FLOATS (TQ * SS_ + TQ * DD + 128 * DD)
#define SMEM_BYTES (SMEM_FLOATS * 4)

__global__ __launch_bounds__(NTHREADS, 1)
void attn_fused_kernel(const float* __restrict__ Q,
                       const float* __restrict__ K,
                       const float* __restrict__ V,
                       const int* __restrict__ pad,
                       float* __restrict__ out_res,
                       float* __restrict__ out_w)
{
    extern __shared__ float smem[];
    float* sS = smem;                   // [TQ][S]
    float* sQ = smem + TQ * SS_;        // [TQ][D]
    float* sV = sQ + TQ * DD;           // [128][D]

    const int b  = blockIdx.z;
    const int h  = blockIdx.y;
    const int q0 = blockIdx.x * TQ;
    const int tid = threadIdx.x;

    const size_t headoff = ((size_t)(b * HH + h)) * SS_ * DD;
    const float* Qh = Q + headoff + (size_t)q0 * DD;
    const float* Kh = K + headoff;
    const float* Vh = V + headoff;
    const int*   padb = pad + b * SS_;

    // ---- load Q tile (coalesced) ----
    for (int i = tid; i < TQ * DD; i += NTHREADS) sQ[i] = Qh[i];
    __syncthreads();

    // ---- Phase 1: scores = Q K^T * 0.125, with mask applied ----
    // Each thread owns 8 columns, processed as 4 passes of 2 columns
    // (c, c + S/2) so each Q smem load feeds 8 FMAs.
    const float scale = 0.125f;  // 1/sqrt(64)
    for (int g = 0; g < 4; ++g) {
        const int c0 = g * NTHREADS + tid;
        const int c1 = c0 + SS_ / 2;
        const float4* K0 = (const float4*)(Kh + (size_t)c0 * DD);
        const float4* K1 = (const float4*)(Kh + (size_t)c1 * DD);

        float acc0[TQ], acc1[TQ];
        #pragma unroll
        for (int q = 0; q < TQ; ++q) { acc0[q] = 0.f; acc1[q] = 0.f; }

        #pragma unroll 4
        for (int d4 = 0; d4 < DD / 4; ++d4) {
            const float4 k0 = K0[d4];
            const float4 k1 = K1[d4];
            #pragma unroll
            for (int q = 0; q < TQ; ++q) {
                const float4 qv = *(const float4*)(sQ + q * DD + d4 * 4);
                acc0[q] += qv.x * k0.x + qv.y * k0.y + qv.z * k0.z + qv.w * k0.w;
                acc1[q] += qv.x * k1.x + qv.y * k1.y + qv.z * k1.z + qv.w * k1.w;
            }
        }

        const int pm0 = padb[c0];
        const int pm1 = padb[c1];
        #pragma unroll
        for (int q = 0; q < TQ; ++q) {
            const int qg = q0 + q;
            const int f0 = (c0 > qg) ? 1 : 0;
            const int f1 = (c1 > qg) ? 1 : 0;
            sS[q * SS_ + c0] = ((f0 + pm0) == 1) ? -1e9f : acc0[q] * scale;
            sS[q * SS_ + c1] = ((f1 + pm1) == 1) ? -1e9f : acc1[q] * scale;
        }
    }
    __syncthreads();

    // ---- Phase 2: row softmax (each warp owns 2 rows) + weights write ----
    const int warp = tid >> 5;
    const int lane = tid & 31;
    for (int r = warp; r < TQ; r += NTHREADS / 32) {
        float* row = sS + (size_t)r * SS_;

        float m = -1e30f;
        for (int c = lane; c < SS_; c += 32) m = fmaxf(m, row[c]);
        #pragma unroll
        for (int o = 16; o > 0; o >>= 1)
            m = fmaxf(m, __shfl_xor_sync(0xffffffffu, m, o));

        if (m <= -5e8f) {
            // degenerate: every column masked -> reference softmax is uniform
            const float u = 1.0f / SS_;
            for (int c = lane; c < SS_; c += 32) row[c] = u;
        } else {
            float sum = 0.f;
            for (int c = lane; c < SS_; c += 32) {
                const float s = row[c];
                const float e = (s <= -5e8f) ? 0.f : __expf(s - m);
                row[c] = e;
                sum += e;
            }
            #pragma unroll
            for (int o = 16; o > 0; o >>= 1)
                sum += __shfl_xor_sync(0xffffffffu, sum, o);
            const float inv = 1.0f / sum;
            for (int c = lane; c < SS_; c += 32) row[c] *= inv;
        }

        if (out_w != nullptr) {
            float* wr = out_w + (((size_t)(b * HH + h)) * SS_ + (q0 + r)) * SS_;
            for (int c = lane; c < SS_; c += 32) wr[c] = row[c];
        }
    }

    // ---- Phase 3: result = P @ V, V staged through smem in 128-row tiles ----
    const int q  = tid >> 4;       // 0..15
    const int d4 = tid & 15;       // float4 index 0..15
    float4 acc = make_float4(0.f, 0.f, 0.f, 0.f);
    float4* sV4 = (float4*)sV;

    for (int kt = 0; kt < SS_ / 128; ++kt) {
        __syncthreads();   // previous tile fully consumed (also fences softmax on kt==0)
        const float4* Vt = (const float4*)(Vh + (size_t)kt * 128 * DD);
        for (int i = tid; i < 128 * (DD / 4); i += NTHREADS) sV4[i] = Vt[i];
        __syncthreads();

        const float* srow = sS + (size_t)q * SS_ + kt * 128;
        #pragma unroll 8
        for (int kk = 0; kk < 128; ++kk) {
            const float w = srow[kk];
            const float4 v = sV4[kk * (DD / 4) + d4];
            acc.x += w * v.x;
            acc.y += w * v.y;
            acc.z += w * v.z;
            acc.w += w * v.w;
        }
    }

    if (out_res != nullptr) {
        float4* orow = (float4*)(out_res + (((size_t)(b * HH + h)) * SS_ + (q0 + q)) * DD);
        orow[d4] = acc;
    }
}

extern "C" void kernel_launch(void* const* d_in, const int* in_sizes, int n_in,
                              void* d_out, int out_size)
{
    const float* Q   = (const float*)d_in[0];
    const float* K   = (const float*)d_in[1];
    const float* V   = (const float*)d_in[2];
    const int*   pad = (const int*)d_in[3];

    const long long RES_N = (long long)BB * HH * SS_ * DD;        //   8,388,608
    const long long W_N   = (long long)BB * HH * SS_ * (long long)SS_;  // 268,435,456

    float* o = (float*)d_out;
    float* out_res = nullptr;
    float* out_w   = nullptr;
    if ((long long)out_size == RES_N) {
        out_res = o;                       // only result checked
    } else if ((long long)out_size == W_N) {
        out_w = o;                         // only weights checked
    } else {
        out_res = o;                       // tuple concatenated: (result, weights)
        out_w   = o + RES_N;
    }

    cudaFuncSetAttribute(attn_fused_kernel,
                         cudaFuncAttributeMaxDynamicSharedMemorySize, SMEM_BYTES);

    dim3 grid(SS_ / TQ, HH, BB);
    attn_fused_kernel<<<grid, NTHREADS, SMEM_BYTES>>>(Q, K, V, pad, out_res, out_w);
}

// round 8
// speedup vs baseline: 3.0579x; 3.0579x over previous
#include <cuda_runtime.h>
#include <cuda_bf16.h>
#include <cstdint>

#define BB 4
#define HH 16
#define SSEQ 2048
#define DDIM 64
#define NHEAD (BB * HH)
#define STRD 72   // bf16 elements per SMEM operand row (pad: conflict-free frags)

// ---------------- mma.sync m16n8k16 bf16 (family-portable, sm_80 baseline) ----
__device__ __forceinline__ void mma_bf16(float* c, const uint32_t* a, const uint32_t* b) {
    asm volatile(
        "mma.sync.aligned.m16n8k16.row.col.f32.bf16.bf16.f32 "
        "{%0,%1,%2,%3}, {%4,%5,%6,%7}, {%8,%9}, {%0,%1,%2,%3};"
        : "+f"(c[0]), "+f"(c[1]), "+f"(c[2]), "+f"(c[3])
        : "r"(a[0]), "r"(a[1]), "r"(a[2]), "r"(a[3]), "r"(b[0]), "r"(b[1]));
}

// split (x,y) into packed bf16x2 hi + bf16x2 lo residual
__device__ __forceinline__ void split2(float x, float y, uint32_t& h, uint32_t& l) {
    __nv_bfloat162 hh = __floats2bfloat162_rn(x, y);
    const float hx = __bfloat162float(__low2bfloat16(hh));
    const float hy = __bfloat162float(__high2bfloat16(hh));
    __nv_bfloat162 ll = __floats2bfloat162_rn(x - hx, y - hy);
    h = *(uint32_t*)&hh;
    l = *(uint32_t*)&ll;
}

// scratch for the (unobserved) result-only output case
__device__ float g_wscratch[(size_t)NHEAD * SSEQ * SSEQ];

// ===================== K1: masked raw scores = (0.125 Q) K^T ==================
// CTA: 128(M) x 128(N), K=64. 8 warps = 4(m) x 2(n); warp tile 32x64.
#define K1_OPBYTES (4 * 128 * STRD * 2)        // 73728
#define K1_SMEM    (K1_OPBYTES + 512)          // + pad[] ints

__global__ void __launch_bounds__(256, 2)
k1_scores(const float* __restrict__ Q, const float* __restrict__ K,
          const int* __restrict__ pad, float* __restrict__ out_w)
{
    extern __shared__ char smem[];
    uint16_t* sQh = (uint16_t*)smem;
    uint16_t* sQl = sQh + 128 * STRD;
    uint16_t* sKh = sQl + 128 * STRD;
    uint16_t* sKl = sKh + 128 * STRD;
    int*      spad = (int*)(smem + K1_OPBYTES);
    float*    so   = (float*)smem;             // epilogue staging (reuse)

    const int tid = threadIdx.x;
    const int wid = tid >> 5, lane = tid & 31;
    const int g = lane >> 2, tq = lane & 3;
    const int head = blockIdx.z;
    const int q0 = blockIdx.x * 128;
    const int c0 = blockIdx.y * 128;

    if (tid < 128) spad[tid] = pad[(head >> 4) * SSEQ + c0 + tid];

    // stage Q (scaled) and K, split hi/lo
    const float4* Qg = (const float4*)(Q + ((size_t)head * SSEQ + q0) * DDIM);
    const float4* Kg = (const float4*)(K + ((size_t)head * SSEQ + c0) * DDIM);
    for (int i = tid; i < 128 * 16; i += 256) {
        const int r = i >> 4, c4 = i & 15;
        float4 v = Qg[i];
        v.x *= 0.125f; v.y *= 0.125f; v.z *= 0.125f; v.w *= 0.125f;
        uint32_t h0, l0, h1, l1;
        split2(v.x, v.y, h0, l0); split2(v.z, v.w, h1, l1);
        uint32_t* dh = (uint32_t*)(sQh + r * STRD + c4 * 4);
        uint32_t* dl = (uint32_t*)(sQl + r * STRD + c4 * 4);
        dh[0] = h0; dh[1] = h1; dl[0] = l0; dl[1] = l1;

        const float4 k = Kg[i];
        split2(k.x, k.y, h0, l0); split2(k.z, k.w, h1, l1);
        dh = (uint32_t*)(sKh + r * STRD + c4 * 4);
        dl = (uint32_t*)(sKl + r * STRD + c4 * 4);
        dh[0] = h0; dh[1] = h1; dl[0] = l0; dl[1] = l1;
    }
    __syncthreads();

    const int mrow = (wid & 3) * 32;
    const int ncol = (wid >> 2) * 64;
    float acc[2][8][4];
    #pragma unroll
    for (int mf = 0; mf < 2; ++mf)
        #pragma unroll
        for (int nf = 0; nf < 8; ++nf)
            #pragma unroll
            for (int j = 0; j < 4; ++j) acc[mf][nf][j] = 0.f;

    #pragma unroll
    for (int pass = 0; pass < 3; ++pass) {
        const uint16_t* A = (pass == 2) ? sQl : sQh;
        const uint16_t* B = (pass == 1) ? sKl : sKh;
        #pragma unroll
        for (int ks = 0; ks < 4; ++ks) {
            const int k0 = ks * 16;
            uint32_t af[2][4];
            #pragma unroll
            for (int mf = 0; mf < 2; ++mf) {
                const uint16_t* p = A + (mrow + mf * 16 + g) * STRD + k0 + 2 * tq;
                af[mf][0] = *(const uint32_t*)p;
                af[mf][1] = *(const uint32_t*)(p + 8 * STRD);
                af[mf][2] = *(const uint32_t*)(p + 8);
                af[mf][3] = *(const uint32_t*)(p + 8 * STRD + 8);
            }
            #pragma unroll
            for (int nf = 0; nf < 8; ++nf) {
                const uint16_t* p = B + (ncol + nf * 8 + g) * STRD + k0 + 2 * tq;
                uint32_t bf[2];
                bf[0] = *(const uint32_t*)p;
                bf[1] = *(const uint32_t*)(p + 8);
                mma_bf16(acc[0][nf], af[0], bf);
                mma_bf16(acc[1][nf], af[1], bf);
            }
        }
    }

    __syncthreads();   // operands consumed; reuse SMEM for staging
    #pragma unroll
    for (int mf = 0; mf < 2; ++mf)
        #pragma unroll
        for (int nf = 0; nf < 8; ++nf) {
            const int r = mrow + mf * 16 + g;
            const int c = ncol + nf * 8 + 2 * tq;
            so[r * 132 + c]           = acc[mf][nf][0];
            so[r * 132 + c + 1]       = acc[mf][nf][1];
            so[(r + 8) * 132 + c]     = acc[mf][nf][2];
            so[(r + 8) * 132 + c + 1] = acc[mf][nf][3];
        }
    __syncthreads();

    // masked coalesced write
    for (int i = tid; i < 128 * 32; i += 256) {
        const int r = i >> 5, c4 = i & 31;
        float4 v = *(const float4*)(so + r * 132 + c4 * 4);
        const int q = q0 + r;
        const int cb = c0 + c4 * 4;
        if ((((cb + 0) > q ? 1 : 0) + spad[c4 * 4 + 0]) == 1) v.x = -1e9f;
        if ((((cb + 1) > q ? 1 : 0) + spad[c4 * 4 + 1]) == 1) v.y = -1e9f;
        if ((((cb + 2) > q ? 1 : 0) + spad[c4 * 4 + 2]) == 1) v.z = -1e9f;
        if ((((cb + 3) > q ? 1 : 0) + spad[c4 * 4 + 3]) == 1) v.w = -1e9f;
        *(float4*)(out_w + ((size_t)head * SSEQ + q0 + r) * SSEQ + cb) = v;
    }
}

// ===================== K2: softmax in place (mask pre-applied) ================
__global__ void __launch_bounds__(256)
k2_softmax(float* __restrict__ w)
{
    const int tid = threadIdx.x, warp = tid >> 5, lane = tid & 31;
    const long long r = (long long)blockIdx.x * 8 + warp;
    float4* row4 = (float4*)(w + (size_t)r * SSEQ);

    float v[64];
    float m = -1e30f;
    #pragma unroll
    for (int i = 0; i < 16; ++i) {
        const float4 s = row4[lane + i * 32];
        v[4*i+0] = s.x; v[4*i+1] = s.y; v[4*i+2] = s.z; v[4*i+3] = s.w;
        m = fmaxf(m, fmaxf(fmaxf(s.x, s.y), fmaxf(s.z, s.w)));
    }
    #pragma unroll
    for (int o = 16; o > 0; o >>= 1) m = fmaxf(m, __shfl_xor_sync(0xffffffffu, m, o));

    if (m <= -5e8f) {   // all masked -> reference softmax is uniform
        const float u = 1.0f / SSEQ;
        const float4 uu = make_float4(u, u, u, u);
        #pragma unroll
        for (int i = 0; i < 16; ++i) row4[lane + i * 32] = uu;
    } else {
        float sum = 0.f;
        #pragma unroll
        for (int i = 0; i < 64; ++i) {
            const float e = __expf(v[i] - m);   // exp(-1e9 - m) underflows to 0
            v[i] = e; sum += e;
        }
        #pragma unroll
        for (int o = 16; o > 0; o >>= 1) sum += __shfl_xor_sync(0xffffffffu, sum, o);
        const float inv = 1.0f / sum;
        #pragma unroll
        for (int i = 0; i < 16; ++i)
            row4[lane + i * 32] = make_float4(v[4*i+0]*inv, v[4*i+1]*inv,
                                              v[4*i+2]*inv, v[4*i+3]*inv);
    }
}

// ===================== K3: O = P V ===========================================
// CTA: 128 q x 64 d, s-tiles of 64. 8 warps = 4(m) x 2(n); warp tile 32x32.
#define K3_PBYTES  (2 * 128 * STRD * 2)                 // 36864
#define K3_VBYTES  (2 * 64 * STRD * 2)                  // 18432
#define K3_RAWOFF  (K3_PBYTES + K3_VBYTES)              // 55296
#define K3_SMEM    (K3_RAWOFF + 64 * 67 * 4)            // 72448

__global__ void __launch_bounds__(256, 2)
k3_pv(const float* __restrict__ W, const float* __restrict__ V, float* __restrict__ O)
{
    extern __shared__ char smem[];
    uint16_t* sPh = (uint16_t*)smem;
    uint16_t* sPl = sPh + 128 * STRD;
    uint16_t* sVh = (uint16_t*)(smem + K3_PBYTES);
    uint16_t* sVl = sVh + 64 * STRD;
    float*    raw = (float*)(smem + K3_RAWOFF);          // [64][67]

    const int tid = threadIdx.x;
    const int wid = tid >> 5, lane = tid & 31;
    const int g = lane >> 2, tq = lane & 3;
    const int head = blockIdx.y;
    const int q0 = blockIdx.x * 128;

    const float4* Wg = (const float4*)(W + (size_t)head * SSEQ * SSEQ);
    const float4* Vg = (const float4*)(V + (size_t)head * SSEQ * DDIM);

    const int mrow = (wid & 3) * 32;
    const int ncol = (wid >> 2) * 32;
    float acc[2][4][4];
    #pragma unroll
    for (int mf = 0; mf < 2; ++mf)
        #pragma unroll
        for (int nf = 0; nf < 4; ++nf)
            #pragma unroll
            for (int j = 0; j < 4; ++j) acc[mf][nf][j] = 0.f;

    for (int t = 0; t < SSEQ / 64; ++t) {
        __syncthreads();   // previous tile operands consumed

        // stage P tile [128 q x 64 s], split hi/lo
        for (int i = tid; i < 128 * 16; i += 256) {
            const int r = i >> 4, c4 = i & 15;
            const float4 p = Wg[(size_t)(q0 + r) * (SSEQ / 4) + t * 16 + c4];
            uint32_t h0, l0, h1, l1;
            split2(p.x, p.y, h0, l0); split2(p.z, p.w, h1, l1);
            uint32_t* dh = (uint32_t*)(sPh + r * STRD + c4 * 4);
            uint32_t* dl = (uint32_t*)(sPl + r * STRD + c4 * 4);
            dh[0] = h0; dh[1] = h1; dl[0] = l0; dl[1] = l1;
        }
        // stage V raw [64 s x 67-padded d]
        for (int i = tid; i < 64 * 16; i += 256) {
            const int s = i >> 4, c4 = i & 15;
            const float4 v = Vg[(size_t)(t * 64 + s) * 16 + c4];
            float* d = raw + s * 67 + c4 * 4;
            d[0] = v.x; d[1] = v.y; d[2] = v.z; d[3] = v.w;
        }
        __syncthreads();

        // transpose V -> [d][s], split hi/lo (reads stride-67: conflict-free)
        {
            const int s = tid & 63, dg = tid >> 6;
            #pragma unroll
            for (int j = 0; j < 16; ++j) {
                const int d = dg * 16 + j;
                const float v = raw[s * 67 + d];
                const __nv_bfloat16 bh = __float2bfloat16(v);
                const float fh = __bfloat162float(bh);
                const __nv_bfloat16 bl = __float2bfloat16(v - fh);
                sVh[d * STRD + s] = __bfloat16_as_ushort(bh);
                sVl[d * STRD + s] = __bfloat16_as_ushort(bl);
            }
        }
        __syncthreads();

        #pragma unroll
        for (int pass = 0; pass < 3; ++pass) {
            const uint16_t* A = (pass == 2) ? sPl : sPh;
            const uint16_t* B = (pass == 1) ? sVl : sVh;
            #pragma unroll
            for (int ks = 0; ks < 4; ++ks) {
                const int k0 = ks * 16;
                uint32_t af[2][4];
                #pragma unroll
                for (int mf = 0; mf < 2; ++mf) {
                    const uint16_t* p = A + (mrow + mf * 16 + g) * STRD + k0 + 2 * tq;
                    af[mf][0] = *(const uint32_t*)p;
                    af[mf][1] = *(const uint32_t*)(p + 8 * STRD);
                    af[mf][2] = *(const uint32_t*)(p + 8);
                    af[mf][3] = *(const uint32_t*)(p + 8 * STRD + 8);
                }
                #pragma unroll
                for (int nf = 0; nf < 4; ++nf) {
                    const uint16_t* p = B + (ncol + nf * 8 + g) * STRD + k0 + 2 * tq;
                    uint32_t bf[2];
                    bf[0] = *(const uint32_t*)p;
                    bf[1] = *(const uint32_t*)(p + 8);
                    mma_bf16(acc[0][nf], af[0], bf);
                    mma_bf16(acc[1][nf], af[1], bf);
                }
            }
        }
    }

    // epilogue: direct gmem writes (O is tiny: 32 MB total)
    #pragma unroll
    for (int mf = 0; mf < 2; ++mf)
        #pragma unroll
        for (int nf = 0; nf < 4; ++nf) {
            const int r = q0 + mrow + mf * 16 + g;
            const int c = ncol + nf * 8 + 2 * tq;
            float* o0 = O + ((size_t)head * SSEQ + r) * DDIM + c;
            *(float2*)o0 = make_float2(acc[mf][nf][0], acc[mf][nf][1]);
            *(float2*)(o0 + 8 * DDIM) = make_float2(acc[mf][nf][2], acc[mf][nf][3]);
        }
}

// ===================== launch =================================================
extern "C" void kernel_launch(void* const* d_in, const int* in_sizes, int n_in,
                              void* d_out, int out_size)
{
    const float* Q   = (const float*)d_in[0];
    const float* K   = (const float*)d_in[1];
    const float* V   = (const float*)d_in[2];
    const int*   pad = (const int*)d_in[3];

    const long long RES_N = (long long)NHEAD * SSEQ * DDIM;
    const long long W_N   = (long long)NHEAD * SSEQ * (long long)SSEQ;

    float* o = (float*)d_out;
    float* out_res = nullptr;
    float* out_w   = nullptr;
    if ((long long)out_size == RES_N) {
        out_res = o;
        cudaGetSymbolAddress((void**)&out_w, g_wscratch);
    } else if ((long long)out_size == W_N) {
        out_w = o;
    } else {
        out_res = o;
        out_w   = o + RES_N;
    }

    cudaFuncSetAttribute(k1_scores, cudaFuncAttributeMaxDynamicSharedMemorySize, K1_SMEM);
    cudaFuncSetAttribute(k3_pv,     cudaFuncAttributeMaxDynamicSharedMemorySize, K3_SMEM);

    k1_scores<<<dim3(SSEQ / 128, SSEQ / 128, NHEAD), 256, K1_SMEM>>>(Q, K, pad, out_w);
    k2_softmax<<<NHEAD * SSEQ / 8, 256>>>(out_w);
    if (out_res)
        k3_pv<<<dim3(SSEQ / 128, NHEAD), 256, K3_SMEM>>>(out_w, V, out_res);
}